// round 8
// baseline (speedup 1.0000x reference)
#include <cuda_runtime.h>
#include <math.h>

typedef unsigned long long ull;

// ---------------- packed f32x2 helpers (Blackwell FFMA2) ----------------
__device__ __forceinline__ ull pk2(float lo, float hi)
{ ull r; asm("mov.b64 %0, {%1, %2};" : "=l"(r) : "f"(lo), "f"(hi)); return r; }
__device__ __forceinline__ void fma2(ull& d, ull a, ull b)
{ asm("fma.rn.f32x2 %0, %1, %2, %0;" : "+l"(d) : "l"(a), "l"(b)); }
__device__ __forceinline__ float2 upk(ull v)
{ float2 r; asm("mov.b64 {%0, %1}, %2;" : "=f"(r.x), "=f"(r.y) : "l"(v)); return r; }

// ---------------- output layout (float32, tuple order) ----------------
#define N_RECON   (16ULL*64*256*256)          // 67108864
#define OFF_Q     (N_RECON)
#define N_Q       (16ULL*4096*128)            // 8388608
#define OFF_IDX   (OFF_Q + N_Q)               // 75497472
#define N_IDX     (16ULL*4096)
#define OFF_LOSS  (OFF_IDX + N_IDX)           // 75563008

// ---------------- scratch (device globals; no allocation) ----------------
__device__ float g_s2[16ULL*128*128*128];   // fused(spec+e1) out [16,128,128,128]
__device__ float g_s3[16ULL*256*64*64];     // e2 out             [16,256,64,64]
__device__ float g_tok[16ULL*128*64*64];    // proj out (tokens, NCHW)
__device__ float g_rec[16ULL*128*64*64];    // recon_feat
__device__ float g_fin[16ULL*64*64*64];     // final 1x1 conv at low res
__device__ int   g_idx[16*4096];
__device__ float g_wt_e1[128*9*128];        // e1 transposed [(h,ky,kx)][oc]
__device__ float g_wt_f[64*9*128];          // fused weights [(ic,ky,kx)][oc]
__device__ float g_tb[9*128];               // spec-bias tap table [kyx][oc]
__device__ float g_wt_e2[128*9*256];
__device__ float g_wt_proj[256*128];
__device__ float g_wt_rec[128*9*128];
__device__ float g_wt_fin[128*64];
__device__ float g_ct[128*1024];            // codebook transposed [k][j]
__device__ float g_cnorm[1024];
__device__ float g_ptab[1025ULL*9*128];     // rec-conv codeword table; row 1024 = zeros
__device__ double g_acc[2];                 // [0]=recon sq sum, [1]=vq sq sum

// ---------------- small helpers ----------------
__global__ void k_init() { g_acc[0] = 0.0; g_acc[1] = 0.0; }

// wt[r*Cout + oc] = w[oc*R + r]
__global__ void k_transpose(const float* __restrict__ w, int Cout, int R, int which)
{
    float* dst = (which==1) ? g_wt_e1 :
                 (which==2) ? g_wt_e2   : (which==3) ? g_wt_proj :
                 (which==4) ? g_wt_rec  : (which==5) ? g_wt_fin : g_ct;
    int i = blockIdx.x * blockDim.x + threadIdx.x;
    if (i < Cout * R) {
        int oc = i / R, r = i - oc * R;
        dst[(size_t)r * Cout + oc] = w[i];
    }
}

__global__ void k_comb(const float* __restrict__ w_spec)
{
    int ic = blockIdx.x, kyx = blockIdx.y, oc = threadIdx.x;
    float s = 0.f;
    #pragma unroll 8
    for (int h = 0; h < 128; h++)
        s = fmaf(g_wt_e1[(size_t)(h * 9 + kyx) * 128 + oc], w_spec[h * 64 + ic], s);
    g_wt_f[(size_t)(ic * 9 + kyx) * 128 + oc] = s;
}

__global__ void k_tapbias(const float* __restrict__ b_spec)
{
    int kyx = blockIdx.x, oc = threadIdx.x;
    float s = 0.f;
    #pragma unroll 8
    for (int h = 0; h < 128; h++)
        s = fmaf(g_wt_e1[(size_t)(h * 9 + kyx) * 128 + oc], b_spec[h], s);
    g_tb[kyx * 128 + oc] = s;
}

__global__ void k_cnorm(const float* __restrict__ cb)
{
    int j = blockIdx.x * blockDim.x + threadIdx.x;
    if (j < 1024) {
        float s = 0.f;
        #pragma unroll 8
        for (int k = 0; k < 128; k++) { float v = cb[j*128+k]; s = fmaf(v, v, s); }
        g_cnorm[j] = s;
    }
}

// rec-conv codeword table
__global__ void k_ptab(const float* __restrict__ cb)
{
    int j = blockIdx.x, kyx = blockIdx.y, oc = threadIdx.x;
    float s = 0.f;
    if (j < 1024) {
        #pragma unroll 8
        for (int c = 0; c < 128; c++)
            s = fmaf(g_wt_rec[(size_t)(c * 9 + kyx) * 128 + oc], cb[j * 128 + c], s);
    }
    g_ptab[((size_t)j * 9 + kyx) * 128 + oc] = s;
}

// ---------------- smem-tiled conv with packed f32x2 FMA ----------------
// Thread: 4 oc x 8 px, pixels packed in pairs (2p, 2p+1). Weights stored
// duplicated {w,w} in smem so each weight load is one LDS.64.
template<int K, int S, int CHUNK, int TOC, bool RELU, bool FUSEB>
__global__ void k_conv_t(const float* __restrict__ in, const float* __restrict__ wt,
                         const float* __restrict__ bias, float* __restrict__ out,
                         int Cin, int Hin, int Win, int Hout, int Wout, int Cout, int nxc)
{
    constexpr int PAD   = (K == 3) ? 1 : 0;
    constexpr int SPAN  = 63 * S + K;           // input x-span for 64 out px
    constexpr int SPAD  = (SPAN + 3) & ~3;
    constexpr int VSPAN = 7 * S + K;            // span for 8 out px
    constexpr int OCW   = TOC / 4;              // threads along oc
    constexpr int NT    = OCW * 8;              // block size

    __shared__ float  s_in[CHUNK][K][SPAD];
    __shared__ float2 s_w[CHUNK * K * K][TOC];  // duplicated {w,w}

    const int t    = threadIdx.x;
    const int ocg  = t % OCW;                   // oc group (4 oc)
    const int px0  = (t / OCW) * 8;             // first pixel of this thread

    const int xc    = blockIdx.x % nxc;
    const int ocblk = blockIdx.x / nxc;
    const int oy    = blockIdx.y;
    const int b     = blockIdx.z;

    const int ix0 = xc * 64 * S - PAD;
    const int iy0 = oy * S - PAD;

    ull acc2[4][4];                             // [oc j][pixel pair]
    #pragma unroll
    for (int j = 0; j < 4; j++)
        #pragma unroll
        for (int p = 0; p < 4; p++) acc2[j][p] = 0ULL;

    const int nchunk = Cin / CHUNK;
    for (int cc = 0; cc < nchunk; cc++) {
        const int ic0 = cc * CHUNK;
        __syncthreads();
        // stage input tile (coalesced along x; zero-pad OOB)
        for (int idx = t; idx < CHUNK * K * SPAN; idx += NT) {
            int ic  = idx / (K * SPAN);
            int rem = idx - ic * (K * SPAN);
            int ky  = rem / SPAN;
            int j   = rem - ky * SPAN;
            int iy = iy0 + ky;
            int ix = ix0 + j;
            float v = 0.f;
            if (iy >= 0 && iy < Hin && ix >= 0 && ix < Win)
                v = in[(((size_t)b * Cin + ic0 + ic) * Hin + iy) * Win + ix];
            s_in[ic][ky][j] = v;
        }
        // stage weight chunk, duplicated per lane of the f32x2
        const float* wsrc = wt + (size_t)(ic0 * K * K) * Cout + ocblk * TOC;
        for (int idx = t; idx < CHUNK * K * K * (TOC / 4); idx += NT) {
            int rr = idx / (TOC / 4);
            int c4 = idx - rr * (TOC / 4);
            float4 w = *(const float4*)(wsrc + (size_t)rr * Cout + c4 * 4);
            s_w[rr][c4 * 4 + 0] = make_float2(w.x, w.x);
            s_w[rr][c4 * 4 + 1] = make_float2(w.y, w.y);
            s_w[rr][c4 * 4 + 2] = make_float2(w.z, w.z);
            s_w[rr][c4 * 4 + 3] = make_float2(w.w, w.w);
        }
        __syncthreads();

        #pragma unroll
        for (int ic = 0; ic < CHUNK; ic++) {
            #pragma unroll
            for (int ky = 0; ky < K; ky++) {
                float v[VSPAN];
                #pragma unroll
                for (int i = 0; i < VSPAN; i++) v[i] = s_in[ic][ky][px0 * S + i];
                #pragma unroll
                for (int kx = 0; kx < K; kx++) {
                    ull x2[4];
                    #pragma unroll
                    for (int p = 0; p < 4; p++)
                        x2[p] = pk2(v[(2*p) * S + kx], v[(2*p+1) * S + kx]);
                    #pragma unroll
                    for (int j = 0; j < 4; j++) {
                        ull w2 = *(const ull*)&s_w[(ic * K + ky) * K + kx][4 * ocg + j];
                        #pragma unroll
                        for (int p = 0; p < 4; p++) fma2(acc2[j][p], w2, x2[p]);
                    }
                }
            }
        }
    }

    #pragma unroll
    for (int j = 0; j < 4; j++) {
        int oc = ocblk * TOC + ocg * 4 + j;
        float bv = bias[oc];
        float lsub = 0.f;
        if (FUSEB) {
            float t00 = g_tb[0*128+oc], t01 = g_tb[1*128+oc], t02 = g_tb[2*128+oc];
            float t10 = g_tb[3*128+oc], t11 = g_tb[4*128+oc], t12 = g_tb[5*128+oc];
            float t20 = g_tb[6*128+oc], t21 = g_tb[7*128+oc], t22 = g_tb[8*128+oc];
            float add = t10+t11+t12 + t20+t21+t22;
            lsub = t10 + t20;
            if (oy > 0) { add += t00+t01+t02; lsub += t00; }
            bv += add;
        }
        float2 a0 = upk(acc2[j][0]), a1 = upk(acc2[j][1]);
        float2 a2 = upk(acc2[j][2]), a3 = upk(acc2[j][3]);
        size_t o = (((size_t)b * Cout + oc) * Hout + oy) * Wout + xc * 64 + px0;
        float4 r0, r1;
        r0.x = a0.x + bv; r0.y = a0.y + bv; r0.z = a1.x + bv; r0.w = a1.y + bv;
        r1.x = a2.x + bv; r1.y = a2.y + bv; r1.z = a3.x + bv; r1.w = a3.y + bv;
        if (FUSEB && xc == 0 && px0 == 0) r0.x -= lsub;   // global ox==0 pixel
        if (RELU) {
            r0.x = fmaxf(r0.x, 0.f); r0.y = fmaxf(r0.y, 0.f);
            r0.z = fmaxf(r0.z, 0.f); r0.w = fmaxf(r0.w, 0.f);
            r1.x = fmaxf(r1.x, 0.f); r1.y = fmaxf(r1.y, 0.f);
            r1.z = fmaxf(r1.z, 0.f); r1.w = fmaxf(r1.w, 0.f);
        }
        *(float4*)(out + o)     = r0;
        *(float4*)(out + o + 4) = r1;
    }
}

// ---------------- VQ with packed f32x2: argmin_j (||C_j||^2 - 2 z.C_j) ----------------
__global__ void k_vq(float* __restrict__ out)
{
    int g  = blockIdx.x;            // 0..8191
    int b  = g >> 9;
    int p0 = (g & 511) << 3;        // token index within batch, multiple of 8
    int t  = threadIdx.x;           // 0..127

    __shared__ float zs[128][8];
    {
        int y = p0 >> 6, x = p0 & 63;
        const float* src = g_tok + (((size_t)(b * 128 + t) * 64 + y) * 64 + x);
        #pragma unroll
        for (int p = 0; p < 8; p++) zs[t][p] = src[p];
    }
    __syncthreads();

    ull acc2[8][4];                 // [token p][code pair]
    #pragma unroll
    for (int p = 0; p < 8; p++)
        #pragma unroll
        for (int j = 0; j < 4; j++) acc2[p][j] = 0ULL;

    for (int k = 0; k < 128; k++) {
        const float* ct = g_ct + (size_t)k * 1024 + t * 8;
        float4 c0 = *(const float4*)ct;
        float4 c1 = *(const float4*)(ct + 4);
        ull cp[4] = { pk2(c0.x, c0.y), pk2(c0.z, c0.w),
                      pk2(c1.x, c1.y), pk2(c1.z, c1.w) };
        #pragma unroll
        for (int p = 0; p < 8; p++) {
            float z = zs[k][p];
            ull z2 = pk2(z, z);
            #pragma unroll
            for (int j = 0; j < 4; j++) fma2(acc2[p][j], cp[j], z2);
        }
    }

    float cn[8];
    #pragma unroll
    for (int j = 0; j < 8; j++) cn[j] = g_cnorm[t * 8 + j];

    __shared__ float s_bd[4][8];
    __shared__ int   s_bi[4][8];
    #pragma unroll
    for (int p = 0; p < 8; p++) {
        float bd = 3.4e38f; int bi = 0;
        #pragma unroll
        for (int j4 = 0; j4 < 4; j4++) {
            float2 a = upk(acc2[p][j4]);
            float d0 = cn[2*j4]   - 2.f * a.x;
            float d1 = cn[2*j4+1] - 2.f * a.y;
            if (d0 < bd) { bd = d0; bi = t * 8 + 2*j4; }
            if (d1 < bd) { bd = d1; bi = t * 8 + 2*j4 + 1; }
        }
        #pragma unroll
        for (int off = 16; off > 0; off >>= 1) {
            float od = __shfl_down_sync(0xffffffffu, bd, off);
            int   oi = __shfl_down_sync(0xffffffffu, bi, off);
            if (od < bd || (od == bd && oi < bi)) { bd = od; bi = oi; }
        }
        if ((t & 31) == 0) { s_bd[t >> 5][p] = bd; s_bi[t >> 5][p] = bi; }
    }
    __syncthreads();
    if (t < 8) {
        float bd = s_bd[0][t]; int bi = s_bi[0][t];
        #pragma unroll
        for (int w = 1; w < 4; w++) {
            float od = s_bd[w][t]; int oi = s_bi[w][t];
            if (od < bd || (od == bd && oi < bi)) { bd = od; bi = oi; }
        }
        int tokid = b * 4096 + p0 + t;
        g_idx[tokid] = bi;
        out[OFF_IDX + tokid] = (float)bi;
    }
}

// ---------------- gather quantized -> output [b,hw,c] + vq-loss partial ----------------
__global__ void k_gather(const float* __restrict__ cb, float* __restrict__ out)
{
    int tok = blockIdx.x;           // 0..65535
    int b = tok >> 12, p = tok & 4095;
    int c = threadIdx.x;            // 0..127
    int idx = g_idx[tok];
    float q = cb[(size_t)idx * 128 + c];
    int y = p >> 6, x = p & 63;
    float tk = g_tok[(((size_t)(b * 128) + c) * 64 + y) * 64 + x];
    out[OFF_Q + (size_t)tok * 128 + c] = q;
    float d = q - tk;
    float v = d * d;
    #pragma unroll
    for (int off = 16; off > 0; off >>= 1) v += __shfl_down_sync(0xffffffffu, v, off);
    __shared__ float sp[4];
    if ((c & 31) == 0) sp[c >> 5] = v;
    __syncthreads();
    if (c == 0) atomicAdd(&g_acc[1], (double)(sp[0] + sp[1] + sp[2] + sp[3]));
}

// ---------------- rec conv via codeword table ----------------
__global__ void k_rec_tab(const float* __restrict__ bias)
{
    int oc = threadIdx.x, y = blockIdx.x, b = blockIdx.y;
    __shared__ int sidx[3][66];     // x in [-1, 64], sentinel 1024 OOB
    for (int i = oc; i < 3 * 66; i += 128) {
        int r  = i / 66;
        int rx = i - r * 66 - 1;
        int ry = y - 1 + r;
        sidx[r][rx + 1] = (ry >= 0 && ry < 64 && rx >= 0 && rx < 64)
                          ? g_idx[b * 4096 + ry * 64 + rx] : 1024;
    }
    __syncthreads();
    float bv = bias[oc];
    float* dst = g_rec + (((size_t)(b * 128 + oc)) * 64 + y) * 64;
    for (int x = 0; x < 64; x += 2) {
        float a0 = bv, a1 = bv;
        #pragma unroll
        for (int ky = 0; ky < 3; ky++) {
            #pragma unroll
            for (int kx = 0; kx < 3; kx++) {
                int j0 = sidx[ky][x + kx];
                int j1 = sidx[ky][x + 1 + kx];
                a0 += g_ptab[((size_t)j0 * 9 + ky * 3 + kx) * 128 + oc];
                a1 += g_ptab[((size_t)j1 * 9 + ky * 3 + kx) * 128 + oc];
            }
        }
        dst[x]     = fmaxf(a0, 0.f);
        dst[x + 1] = fmaxf(a1, 0.f);
    }
}

// ---------------- bilinear 4x upsample of g_fin (+recon loss) ----------------
__global__ void k_upsample(const float* __restrict__ x, float* __restrict__ out)
{
    int t  = threadIdx.x;
    int oc = t & 63;
    int xg = t >> 6;                // 0..3 -> 16 out px each
    int xc = blockIdx.x, oy = blockIdx.y, b = blockIdx.z;

    float sy = (oy + 0.5f) * 0.25f - 0.5f;
    int   y0 = (int)floorf(sy);
    float fy = sy - (float)y0;
    int y0c = min(63, max(0, y0));
    int y1c = min(63, max(0, y0 + 1));

    __shared__ float sf[2][64][19];
    for (int idx = t; idx < 2 * 64 * 18; idx += 256) {
        int row = idx / (64 * 18);
        int rem = idx - row * 64 * 18;
        int c   = rem / 18;
        int sx  = rem - c * 18;
        int gx = min(63, max(0, 16 * xc - 1 + sx));
        int gy = row ? y1c : y0c;
        sf[row][c][sx] = g_fin[(((size_t)b * 64 + c) * 64 + gy) * 64 + gx];
    }
    __syncthreads();

    float ls = 0.f;
    size_t obase = (((size_t)b * 64 + oc) * 256 + oy) * 256 + 64 * xc + 16 * xg;
    const float* xr = x + obase;
    #pragma unroll
    for (int q = 0; q < 4; q++) {
        float4 r;
        float* rp = &r.x;
        #pragma unroll
        for (int i = 0; i < 4; i++) {
            int px = 64 * xc + 16 * xg + 4 * q + i;
            float sx = (px + 0.5f) * 0.25f - 0.5f;
            int   x0 = (int)floorf(sx);
            float fx = sx - (float)x0;
            int l0 = x0 - (16 * xc - 1);
            l0 = min(17, max(0, l0));
            int l1 = min(17, l0 + 1);
            float t0 = sf[0][oc][l0]; float t1 = sf[0][oc][l1];
            float b0 = sf[1][oc][l0]; float b1 = sf[1][oc][l1];
            float top = t0 + fx * (t1 - t0);
            float bot = b0 + fx * (b1 - b0);
            rp[i] = top + fy * (bot - top);
        }
        *(float4*)(out + obase + 4 * q) = r;
        float4 xv = *(const float4*)(xr + 4 * q);
        float d0 = r.x - xv.x, d1 = r.y - xv.y, d2 = r.z - xv.z, d3 = r.w - xv.w;
        ls = fmaf(d0, d0, ls); ls = fmaf(d1, d1, ls);
        ls = fmaf(d2, d2, ls); ls = fmaf(d3, d3, ls);
    }
    #pragma unroll
    for (int off = 16; off > 0; off >>= 1) ls += __shfl_down_sync(0xffffffffu, ls, off);
    __shared__ float sp[8];
    if ((t & 31) == 0) sp[t >> 5] = ls;
    __syncthreads();
    if (t == 0) {
        float s = 0.f;
        #pragma unroll
        for (int w = 0; w < 8; w++) s += sp[w];
        atomicAdd(&g_acc[0], (double)s);
    }
}

__global__ void k_finalize(float* __restrict__ out)
{
    double rl = g_acc[0] / (double)N_RECON;
    double vq = g_acc[1] * 1.25 / (double)N_Q;   // (1+BETA)*mean((q-z)^2)
    out[OFF_LOSS + 0] = (float)(rl + vq);
    out[OFF_LOSS + 1] = (float)rl;
    out[OFF_LOSS + 2] = (float)vq;
}

// ---------------- launch ----------------
extern "C" void kernel_launch(void* const* d_in, const int* in_sizes, int n_in,
                              void* d_out, int out_size)
{
    const float* x      = (const float*)d_in[0];
    const float* w_spec = (const float*)d_in[1];
    const float* b_spec = (const float*)d_in[2];
    const float* w_e1   = (const float*)d_in[3];
    const float* b_e1   = (const float*)d_in[4];
    const float* w_e2   = (const float*)d_in[5];
    const float* b_e2   = (const float*)d_in[6];
    const float* w_proj = (const float*)d_in[7];
    const float* b_proj = (const float*)d_in[8];
    const float* cb     = (const float*)d_in[9];
    const float* w_rec  = (const float*)d_in[10];
    const float* b_rec  = (const float*)d_in[11];
    const float* w_fin  = (const float*)d_in[12];
    const float* b_fin  = (const float*)d_in[13];
    float* out = (float*)d_out;

    float *s2, *s3, *tok, *rec, *fin;
    float *wt_f, *wt_e2, *wt_proj, *wt_fin;
    cudaGetSymbolAddress((void**)&s2,   g_s2);
    cudaGetSymbolAddress((void**)&s3,   g_s3);
    cudaGetSymbolAddress((void**)&tok,  g_tok);
    cudaGetSymbolAddress((void**)&rec,  g_rec);
    cudaGetSymbolAddress((void**)&fin,  g_fin);
    cudaGetSymbolAddress((void**)&wt_f,    g_wt_f);
    cudaGetSymbolAddress((void**)&wt_e2,   g_wt_e2);
    cudaGetSymbolAddress((void**)&wt_proj, g_wt_proj);
    cudaGetSymbolAddress((void**)&wt_fin,  g_wt_fin);

    k_init<<<1, 1>>>();

    // weight prep
    k_transpose<<<(128*1152 + 255) / 256, 256>>>(w_e1,   128, 1152, 1);
    k_transpose<<<(256*1152 + 255) / 256, 256>>>(w_e2,   256, 1152, 2);
    k_transpose<<<(128*256  + 255) / 256, 256>>>(w_proj, 128, 256,  3);
    k_transpose<<<(128*1152 + 255) / 256, 256>>>(w_rec,  128, 1152, 4);
    k_transpose<<<(64*128   + 255) / 256, 256>>>(w_fin,  64,  128,  5);
    k_transpose<<<(1024*128 + 255) / 256, 256>>>(cb,     1024, 128, 6);
    k_comb<<<dim3(64, 9), 128>>>(w_spec);
    k_tapbias<<<9, 128>>>(b_spec);
    k_cnorm<<<4, 256>>>(cb);
    k_ptab<<<dim3(1025, 9), 128>>>(cb);

    // fused spec+e1: 3x3 s2, 64->128, 256->128 (on x directly)
    k_conv_t<3,2,4,128,true,true><<<dim3(2, 128, 16), 256>>>(x, wt_f, b_e1, s2,
                                                             64, 256, 256, 128, 128, 128, 2);
    // e2: 3x3 s2, 128->256, 128->64 (2 oc-blocks)
    k_conv_t<3,2,4,128,true,false><<<dim3(2, 64, 16), 256>>>(s2, wt_e2, b_e2, s3,
                                                             128, 128, 128, 64, 64, 256, 1);
    // proj: 1x1, 256->128, 64x64
    k_conv_t<1,1,16,128,false,false><<<dim3(1, 64, 16), 256>>>(s3, wt_proj, b_proj, tok,
                                                               256, 64, 64, 64, 64, 128, 1);
    // VQ argmin + indices
    k_vq<<<8192, 128>>>(out);
    // gather quantized -> output block + vq loss
    k_gather<<<65536, 128>>>(cb, out);
    // rec conv via codeword table
    k_rec_tab<<<dim3(64, 16), 128>>>(b_rec);
    // fin: 1x1, 128->64 at LOW res (commuted with upsample), bias included
    k_conv_t<1,1,16,64,false,false><<<dim3(1, 64, 16), 128>>>(rec, wt_fin, b_fin, fin,
                                                              128, 64, 64, 64, 64, 64, 1);
    // bilinear 4x upsample + recon output + recon loss
    k_upsample<<<dim3(4, 256, 16), 256>>>(x, out);

    k_finalize<<<1, 1>>>(out);
}

// round 10
// speedup vs baseline: 1.3372x; 1.3372x over previous
#include <cuda_runtime.h>
#include <math.h>

// ---------------- output layout (float32, tuple order) ----------------
#define N_RECON   (16ULL*64*256*256)          // 67108864
#define OFF_Q     (N_RECON)
#define N_Q       (16ULL*4096*128)            // 8388608
#define OFF_IDX   (OFF_Q + N_Q)               // 75497472
#define N_IDX     (16ULL*4096)
#define OFF_LOSS  (OFF_IDX + N_IDX)           // 75563008

// ---------------- scratch (device globals; no allocation) ----------------
__device__ float g_s2[16ULL*128*128*128];   // fused(spec+e1) out [16,128,128,128]
__device__ float g_s3[16ULL*256*64*64];     // e2 out             [16,256,64,64]
__device__ float g_tok[16ULL*128*64*64];    // proj out (tokens, NCHW)
__device__ float g_rec[16ULL*128*64*64];    // recon_feat
__device__ float g_fin[16ULL*64*64*64];     // final 1x1 conv at low res
__device__ int   g_idx[16*4096];
__device__ float g_wt_e1[128*9*128];        // e1 transposed [(h,ky,kx)][oc]
__device__ float g_wt_f[64*9*128];          // fused weights [(ic,ky,kx)][oc]
__device__ float g_tb[9*128];               // spec-bias tap table [kyx][oc]
__device__ float g_wt_e2[128*9*256];
__device__ float g_wt_proj[256*128];
__device__ float g_wt_rec[128*9*128];
__device__ float g_wt_fin[128*64];
__device__ float g_ct[128*1024];            // codebook transposed [k][j]
__device__ float g_cnorm[1024];
__device__ float g_ptab[1025ULL*9*128];     // rec-conv codeword table; row 1024 = zeros
__device__ double g_acc[2];                 // [0]=recon sq sum, [1]=vq sq sum

// ---------------- small helpers ----------------
__global__ void k_init() { g_acc[0] = 0.0; g_acc[1] = 0.0; }

// wt[r*Cout + oc] = w[oc*R + r]
__global__ void k_transpose(const float* __restrict__ w, int Cout, int R, int which)
{
    float* dst = (which==1) ? g_wt_e1 :
                 (which==2) ? g_wt_e2   : (which==3) ? g_wt_proj :
                 (which==4) ? g_wt_rec  : (which==5) ? g_wt_fin : g_ct;
    int i = blockIdx.x * blockDim.x + threadIdx.x;
    if (i < Cout * R) {
        int oc = i / R, r = i - oc * R;
        dst[(size_t)r * Cout + oc] = w[i];
    }
}

__global__ void k_comb(const float* __restrict__ w_spec)
{
    int ic = blockIdx.x, kyx = blockIdx.y, oc = threadIdx.x;
    float s = 0.f;
    #pragma unroll 8
    for (int h = 0; h < 128; h++)
        s = fmaf(g_wt_e1[(size_t)(h * 9 + kyx) * 128 + oc], w_spec[h * 64 + ic], s);
    g_wt_f[(size_t)(ic * 9 + kyx) * 128 + oc] = s;
}

__global__ void k_tapbias(const float* __restrict__ b_spec)
{
    int kyx = blockIdx.x, oc = threadIdx.x;
    float s = 0.f;
    #pragma unroll 8
    for (int h = 0; h < 128; h++)
        s = fmaf(g_wt_e1[(size_t)(h * 9 + kyx) * 128 + oc], b_spec[h], s);
    g_tb[kyx * 128 + oc] = s;
}

__global__ void k_cnorm(const float* __restrict__ cb)
{
    int j = blockIdx.x * blockDim.x + threadIdx.x;
    if (j < 1024) {
        float s = 0.f;
        #pragma unroll 8
        for (int k = 0; k < 128; k++) { float v = cb[j*128+k]; s = fmaf(v, v, s); }
        g_cnorm[j] = s;
    }
}

// rec-conv codeword table
__global__ void k_ptab(const float* __restrict__ cb)
{
    int j = blockIdx.x, kyx = blockIdx.y, oc = threadIdx.x;
    float s = 0.f;
    if (j < 1024) {
        #pragma unroll 8
        for (int c = 0; c < 128; c++)
            s = fmaf(g_wt_rec[(size_t)(c * 9 + kyx) * 128 + oc], cb[j * 128 + c], s);
    }
    g_ptab[((size_t)j * 9 + kyx) * 128 + oc] = s;
}

// ---------------- smem-tiled direct conv (scalar fp32 — R7 proven) ----------------
template<int K, int S, int CHUNK, int TOC, bool RELU, bool FUSEB>
__global__ void k_conv_t(const float* __restrict__ in, const float* __restrict__ wt,
                         const float* __restrict__ bias, float* __restrict__ out,
                         int Cin, int Hin, int Win, int Hout, int Wout, int Cout, int nxc)
{
    constexpr int PAD   = (K == 3) ? 1 : 0;
    constexpr int SPAN  = 63 * S + K;           // input x-span for 64 out px
    constexpr int SPAD  = (SPAN + 3) & ~3;
    constexpr int VSPAN = 7 * S + K;            // span for 8 out px
    constexpr int OCW   = TOC / 4;              // threads along oc
    constexpr int NT    = OCW * 8;              // block size

    __shared__ float s_in[CHUNK][K][SPAD];
    __shared__ float s_w[CHUNK * K * K][TOC];

    const int t    = threadIdx.x;
    const int ocg  = t % OCW;                   // oc group (4 oc)
    const int px0  = (t / OCW) * 8;             // first pixel of this thread

    const int xc    = blockIdx.x % nxc;
    const int ocblk = blockIdx.x / nxc;
    const int oy    = blockIdx.y;
    const int b     = blockIdx.z;

    const int ix0 = xc * 64 * S - PAD;
    const int iy0 = oy * S - PAD;

    float acc[4][8];
    #pragma unroll
    for (int j = 0; j < 4; j++)
        #pragma unroll
        for (int p = 0; p < 8; p++) acc[j][p] = 0.f;

    const int nchunk = Cin / CHUNK;
    for (int cc = 0; cc < nchunk; cc++) {
        const int ic0 = cc * CHUNK;
        __syncthreads();
        // stage input tile (coalesced along x; zero-pad OOB)
        for (int idx = t; idx < CHUNK * K * SPAN; idx += NT) {
            int ic  = idx / (K * SPAN);
            int rem = idx - ic * (K * SPAN);
            int ky  = rem / SPAN;
            int j   = rem - ky * SPAN;
            int iy = iy0 + ky;
            int ix = ix0 + j;
            float v = 0.f;
            if (iy >= 0 && iy < Hin && ix >= 0 && ix < Win)
                v = in[(((size_t)b * Cin + ic0 + ic) * Hin + iy) * Win + ix];
            s_in[ic][ky][j] = v;
        }
        // stage weight chunk (float4, contiguous rows)
        const float* wsrc = wt + (size_t)(ic0 * K * K) * Cout + ocblk * TOC;
        for (int idx = t; idx < CHUNK * K * K * (TOC / 4); idx += NT) {
            int rr = idx / (TOC / 4);
            int c4 = idx - rr * (TOC / 4);
            float4 w = *(const float4*)(wsrc + (size_t)rr * Cout + c4 * 4);
            *(float4*)&s_w[rr][c4 * 4] = w;
        }
        __syncthreads();

        #pragma unroll
        for (int ic = 0; ic < CHUNK; ic++) {
            #pragma unroll
            for (int ky = 0; ky < K; ky++) {
                float v[VSPAN];
                #pragma unroll
                for (int i = 0; i < VSPAN; i++) v[i] = s_in[ic][ky][px0 * S + i];
                #pragma unroll
                for (int kx = 0; kx < K; kx++) {
                    float4 w = *(const float4*)&s_w[(ic * K + ky) * K + kx][4 * ocg];
                    #pragma unroll
                    for (int p = 0; p < 8; p++) {
                        float xv = v[p * S + kx];
                        acc[0][p] = fmaf(w.x, xv, acc[0][p]);
                        acc[1][p] = fmaf(w.y, xv, acc[1][p]);
                        acc[2][p] = fmaf(w.z, xv, acc[2][p]);
                        acc[3][p] = fmaf(w.w, xv, acc[3][p]);
                    }
                }
            }
        }
    }

    #pragma unroll
    for (int j = 0; j < 4; j++) {
        int oc = ocblk * TOC + ocg * 4 + j;
        float bv = bias[oc];
        float lsub = 0.f;
        if (FUSEB) {
            float t00 = g_tb[0*128+oc], t01 = g_tb[1*128+oc], t02 = g_tb[2*128+oc];
            float t10 = g_tb[3*128+oc], t11 = g_tb[4*128+oc], t12 = g_tb[5*128+oc];
            float t20 = g_tb[6*128+oc], t21 = g_tb[7*128+oc], t22 = g_tb[8*128+oc];
            float add = t10+t11+t12 + t20+t21+t22;
            lsub = t10 + t20;
            if (oy > 0) { add += t00+t01+t02; lsub += t00; }
            bv += add;
        }
        size_t o = (((size_t)b * Cout + oc) * Hout + oy) * Wout + xc * 64 + px0;
        float4 r0, r1;
        r0.x = acc[j][0] + bv; r0.y = acc[j][1] + bv;
        r0.z = acc[j][2] + bv; r0.w = acc[j][3] + bv;
        r1.x = acc[j][4] + bv; r1.y = acc[j][5] + bv;
        r1.z = acc[j][6] + bv; r1.w = acc[j][7] + bv;
        if (FUSEB && xc == 0 && px0 == 0) r0.x -= lsub;   // global ox==0 pixel
        if (RELU) {
            r0.x = fmaxf(r0.x, 0.f); r0.y = fmaxf(r0.y, 0.f);
            r0.z = fmaxf(r0.z, 0.f); r0.w = fmaxf(r0.w, 0.f);
            r1.x = fmaxf(r1.x, 0.f); r1.y = fmaxf(r1.y, 0.f);
            r1.z = fmaxf(r1.z, 0.f); r1.w = fmaxf(r1.w, 0.f);
        }
        *(float4*)(out + o)     = r0;
        *(float4*)(out + o + 4) = r1;
    }
}

// ---------------- VQ + gather fused: argmin, idx out, quantized out, vq loss ----------------
__global__ void k_vq(const float* __restrict__ cb, float* __restrict__ out)
{
    int g  = blockIdx.x;            // 0..8191
    int b  = g >> 9;
    int p0 = (g & 511) << 3;        // token index within batch, multiple of 8
    int t  = threadIdx.x;           // 0..127

    __shared__ float zs[128][8];
    {
        int y = p0 >> 6, x = p0 & 63;
        const float* src = g_tok + (((size_t)(b * 128 + t) * 64 + y) * 64 + x);
        #pragma unroll
        for (int p = 0; p < 8; p++) zs[t][p] = src[p];
    }
    __syncthreads();

    float acc[8][8];
    #pragma unroll
    for (int p = 0; p < 8; p++)
        #pragma unroll
        for (int j = 0; j < 8; j++) acc[p][j] = 0.f;

    for (int k = 0; k < 128; k++) {
        const float* ct = g_ct + (size_t)k * 1024 + t * 8;
        float4 c0 = *(const float4*)ct;
        float4 c1 = *(const float4*)(ct + 4);
        float cv[8] = {c0.x, c0.y, c0.z, c0.w, c1.x, c1.y, c1.z, c1.w};
        #pragma unroll
        for (int p = 0; p < 8; p++) {
            float z = zs[k][p];
            #pragma unroll
            for (int j = 0; j < 8; j++) acc[p][j] = fmaf(cv[j], z, acc[p][j]);
        }
    }

    float cn[8];
    #pragma unroll
    for (int j = 0; j < 8; j++) cn[j] = g_cnorm[t * 8 + j];

    __shared__ float s_bd[4][8];
    __shared__ int   s_bi[4][8];
    __shared__ int   s_win[8];
    #pragma unroll
    for (int p = 0; p < 8; p++) {
        float bd = 3.4e38f; int bi = 0;
        #pragma unroll
        for (int j = 0; j < 8; j++) {
            float d = cn[j] - 2.f * acc[p][j];
            if (d < bd) { bd = d; bi = t * 8 + j; }
        }
        #pragma unroll
        for (int off = 16; off > 0; off >>= 1) {
            float od = __shfl_down_sync(0xffffffffu, bd, off);
            int   oi = __shfl_down_sync(0xffffffffu, bi, off);
            if (od < bd || (od == bd && oi < bi)) { bd = od; bi = oi; }
        }
        if ((t & 31) == 0) { s_bd[t >> 5][p] = bd; s_bi[t >> 5][p] = bi; }
    }
    __syncthreads();
    if (t < 8) {
        float bd = s_bd[0][t]; int bi = s_bi[0][t];
        #pragma unroll
        for (int w = 1; w < 4; w++) {
            float od = s_bd[w][t]; int oi = s_bi[w][t];
            if (od < bd || (od == bd && oi < bi)) { bd = od; bi = oi; }
        }
        int tokid = b * 4096 + p0 + t;
        g_idx[tokid] = bi;
        out[OFF_IDX + tokid] = (float)bi;
        s_win[t] = bi;
    }
    __syncthreads();

    // gather quantized rows for the 8 tokens, write output block, vq-loss partial
    float ls = 0.f;
    size_t qbase = OFF_Q + ((size_t)(b * 4096 + p0)) * 128;
    #pragma unroll
    for (int p = 0; p < 8; p++) {
        float q = cb[(size_t)s_win[p] * 128 + t];
        out[qbase + (size_t)p * 128 + t] = q;
        float d = q - zs[t][p];
        ls = fmaf(d, d, ls);
    }
    #pragma unroll
    for (int off = 16; off > 0; off >>= 1) ls += __shfl_down_sync(0xffffffffu, ls, off);
    __shared__ float sp[4];
    if ((t & 31) == 0) sp[t >> 5] = ls;
    __syncthreads();
    if (t == 0) atomicAdd(&g_acc[1], (double)(sp[0] + sp[1] + sp[2] + sp[3]));
}

// ---------------- rec conv via codeword table ----------------
__global__ void k_rec_tab(const float* __restrict__ bias)
{
    int oc = threadIdx.x, y = blockIdx.x, b = blockIdx.y;
    __shared__ int sidx[3][66];     // x in [-1, 64], sentinel 1024 OOB
    for (int i = oc; i < 3 * 66; i += 128) {
        int r  = i / 66;
        int rx = i - r * 66 - 1;
        int ry = y - 1 + r;
        sidx[r][rx + 1] = (ry >= 0 && ry < 64 && rx >= 0 && rx < 64)
                          ? g_idx[b * 4096 + ry * 64 + rx] : 1024;
    }
    __syncthreads();
    float bv = bias[oc];
    float* dst = g_rec + (((size_t)(b * 128 + oc)) * 64 + y) * 64;
    for (int x = 0; x < 64; x += 2) {
        float a0 = bv, a1 = bv;
        #pragma unroll
        for (int ky = 0; ky < 3; ky++) {
            #pragma unroll
            for (int kx = 0; kx < 3; kx++) {
                int j0 = sidx[ky][x + kx];
                int j1 = sidx[ky][x + 1 + kx];
                a0 += g_ptab[((size_t)j0 * 9 + ky * 3 + kx) * 128 + oc];
                a1 += g_ptab[((size_t)j1 * 9 + ky * 3 + kx) * 128 + oc];
            }
        }
        dst[x]     = fmaxf(a0, 0.f);
        dst[x + 1] = fmaxf(a1, 0.f);
    }
}

// ---------------- bilinear 4x upsample of g_fin (+recon loss) ----------------
__global__ void k_upsample(const float* __restrict__ x, float* __restrict__ out)
{
    int t  = threadIdx.x;
    int oc = t & 63;
    int xg = t >> 6;                // 0..3 -> 16 out px each
    int xc = blockIdx.x, oy = blockIdx.y, b = blockIdx.z;

    float sy = (oy + 0.5f) * 0.25f - 0.5f;
    int   y0 = (int)floorf(sy);
    float fy = sy - (float)y0;
    int y0c = min(63, max(0, y0));
    int y1c = min(63, max(0, y0 + 1));

    __shared__ float sf[2][64][19];
    for (int idx = t; idx < 2 * 64 * 18; idx += 256) {
        int row = idx / (64 * 18);
        int rem = idx - row * 64 * 18;
        int c   = rem / 18;
        int sx  = rem - c * 18;
        int gx = min(63, max(0, 16 * xc - 1 + sx));
        int gy = row ? y1c : y0c;
        sf[row][c][sx] = g_fin[(((size_t)b * 64 + c) * 64 + gy) * 64 + gx];
    }
    __syncthreads();

    float ls = 0.f;
    size_t obase = (((size_t)b * 64 + oc) * 256 + oy) * 256 + 64 * xc + 16 * xg;
    const float* xr = x + obase;
    #pragma unroll
    for (int q = 0; q < 4; q++) {
        float4 r;
        float* rp = &r.x;
        #pragma unroll
        for (int i = 0; i < 4; i++) {
            int px = 64 * xc + 16 * xg + 4 * q + i;
            float sx = (px + 0.5f) * 0.25f - 0.5f;
            int   x0 = (int)floorf(sx);
            float fx = sx - (float)x0;
            int l0 = x0 - (16 * xc - 1);
            l0 = min(17, max(0, l0));
            int l1 = min(17, l0 + 1);
            float t0 = sf[0][oc][l0]; float t1 = sf[0][oc][l1];
            float b0 = sf[1][oc][l0]; float b1 = sf[1][oc][l1];
            float top = t0 + fx * (t1 - t0);
            float bot = b0 + fx * (b1 - b0);
            rp[i] = top + fy * (bot - top);
        }
        *(float4*)(out + obase + 4 * q) = r;
        float4 xv = *(const float4*)(xr + 4 * q);
        float d0 = r.x - xv.x, d1 = r.y - xv.y, d2 = r.z - xv.z, d3 = r.w - xv.w;
        ls = fmaf(d0, d0, ls); ls = fmaf(d1, d1, ls);
        ls = fmaf(d2, d2, ls); ls = fmaf(d3, d3, ls);
    }
    #pragma unroll
    for (int off = 16; off > 0; off >>= 1) ls += __shfl_down_sync(0xffffffffu, ls, off);
    __shared__ float sp[8];
    if ((t & 31) == 0) sp[t >> 5] = ls;
    __syncthreads();
    if (t == 0) {
        float s = 0.f;
        #pragma unroll
        for (int w = 0; w < 8; w++) s += sp[w];
        atomicAdd(&g_acc[0], (double)s);
    }
}

__global__ void k_finalize(float* __restrict__ out)
{
    double rl = g_acc[0] / (double)N_RECON;
    double vq = g_acc[1] * 1.25 / (double)N_Q;   // (1+BETA)*mean((q-z)^2)
    out[OFF_LOSS + 0] = (float)(rl + vq);
    out[OFF_LOSS + 1] = (float)rl;
    out[OFF_LOSS + 2] = (float)vq;
}

// ---------------- launch ----------------
extern "C" void kernel_launch(void* const* d_in, const int* in_sizes, int n_in,
                              void* d_out, int out_size)
{
    const float* x      = (const float*)d_in[0];
    const float* w_spec = (const float*)d_in[1];
    const float* b_spec = (const float*)d_in[2];
    const float* w_e1   = (const float*)d_in[3];
    const float* b_e1   = (const float*)d_in[4];
    const float* w_e2   = (const float*)d_in[5];
    const float* b_e2   = (const float*)d_in[6];
    const float* w_proj = (const float*)d_in[7];
    const float* b_proj = (const float*)d_in[8];
    const float* cb     = (const float*)d_in[9];
    const float* w_rec  = (const float*)d_in[10];
    const float* b_rec  = (const float*)d_in[11];
    const float* w_fin  = (const float*)d_in[12];
    const float* b_fin  = (const float*)d_in[13];
    float* out = (float*)d_out;

    float *s2, *s3, *tok, *rec, *fin;
    float *wt_f, *wt_e2, *wt_proj, *wt_fin;
    cudaGetSymbolAddress((void**)&s2,   g_s2);
    cudaGetSymbolAddress((void**)&s3,   g_s3);
    cudaGetSymbolAddress((void**)&tok,  g_tok);
    cudaGetSymbolAddress((void**)&rec,  g_rec);
    cudaGetSymbolAddress((void**)&fin,  g_fin);
    cudaGetSymbolAddress((void**)&wt_f,    g_wt_f);
    cudaGetSymbolAddress((void**)&wt_e2,   g_wt_e2);
    cudaGetSymbolAddress((void**)&wt_proj, g_wt_proj);
    cudaGetSymbolAddress((void**)&wt_fin,  g_wt_fin);

    k_init<<<1, 1>>>();

    // weight prep
    k_transpose<<<(128*1152 + 255) / 256, 256>>>(w_e1,   128, 1152, 1);
    k_transpose<<<(256*1152 + 255) / 256, 256>>>(w_e2,   256, 1152, 2);
    k_transpose<<<(128*256  + 255) / 256, 256>>>(w_proj, 128, 256,  3);
    k_transpose<<<(128*1152 + 255) / 256, 256>>>(w_rec,  128, 1152, 4);
    k_transpose<<<(64*128   + 255) / 256, 256>>>(w_fin,  64,  128,  5);
    k_transpose<<<(1024*128 + 255) / 256, 256>>>(cb,     1024, 128, 6);
    k_comb<<<dim3(64, 9), 128>>>(w_spec);
    k_tapbias<<<9, 128>>>(b_spec);
    k_cnorm<<<4, 256>>>(cb);
    k_ptab<<<dim3(1025, 9), 128>>>(cb);

    // fused spec+e1: 3x3 s2, 64->128, 256->128 (on x directly)
    k_conv_t<3,2,4,128,true,true><<<dim3(2, 128, 16), 256>>>(x, wt_f, b_e1, s2,
                                                             64, 256, 256, 128, 128, 128, 2);
    // e2: 3x3 s2, 128->256, 128->64 (2 oc-blocks)
    k_conv_t<3,2,4,128,true,false><<<dim3(2, 64, 16), 256>>>(s2, wt_e2, b_e2, s3,
                                                             128, 128, 128, 64, 64, 256, 1);
    // proj: 1x1, 256->128, 64x64
    k_conv_t<1,1,16,128,false,false><<<dim3(1, 64, 16), 256>>>(s3, wt_proj, b_proj, tok,
                                                               256, 64, 64, 64, 64, 128, 1);
    // VQ argmin + indices + quantized output + vq loss (fused)
    k_vq<<<8192, 128>>>(cb, out);
    // rec conv via codeword table
    k_rec_tab<<<dim3(64, 16), 128>>>(b_rec);
    // fin: 1x1, 128->64 at LOW res (commuted with upsample), bias included
    k_conv_t<1,1,16,64,false,false><<<dim3(1, 64, 16), 128>>>(rec, wt_fin, b_fin, fin,
                                                              128, 64, 64, 64, 64, 64, 1);
    // bilinear 4x upsample + recon output + recon loss
    k_upsample<<<dim3(4, 256, 16), 256>>>(x, out);

    k_finalize<<<1, 1>>>(out);
}